// round 5
// baseline (speedup 1.0000x reference)
#include <cuda_runtime.h>

// Problem constants (fixed shapes)
#define NN   65536
#define BB   64
#define NPGc 1024
#define CCc  512
#define EEc  2097152
#define DEc  16
#define KKc  512
#define BKc  32768

// Output layout (float32, reference-return order)
#define OFF_XNEW  0LL
#define OFF_EI    16777216LL
#define OFF_EA    20971520LL
#define OFF_MASK  54525952LL
#define OFF_BATCH 56623104LL
#define OFF_PERM  56655872LL

// Scratch. Invariant: g_degE is zero at entry and restored each replay.
__device__ float g_h[NN];       // h, then hd = h*dinv
__device__ float g_dinv[NN];
__device__ float g_score[NN];
__device__ int   g_degE[NN];
__device__ int   g_newidx[NN];
__device__ int   g_perm[BKc];

#define PROJ_BLOCKS 8192
#define DEG_BLOCKS  2048

// K1: fused  h = x@W (warp/row)  ||  in-degree atomics (4 edges/thread)
__global__ void k_proj_deg(const float* __restrict__ x, const float* __restrict__ W,
                           const int* __restrict__ dst) {
    if (blockIdx.x < PROJ_BLOCKS) {
        int warp = (blockIdx.x * blockDim.x + threadIdx.x) >> 5;
        int lane = threadIdx.x & 31;
        const float4* xr = (const float4*)(x + (size_t)warp * CCc);
        const float4* w4 = (const float4*)W;
        float s = 0.f;
#pragma unroll
        for (int i = 0; i < 4; i++) {
            float4 a = xr[lane + i * 32];
            float4 w = w4[lane + i * 32];
            s += a.x * w.x + a.y * w.y + a.z * w.z + a.w * w.w;
        }
#pragma unroll
        for (int o = 16; o; o >>= 1) s += __shfl_down_sync(0xffffffffu, s, o);
        if (lane == 0) {
            g_h[warp] = s;
            g_newidx[warp] = -1;
        }
    } else {
        int idx = (blockIdx.x - PROJ_BLOCKS) * 256 + threadIdx.x;   // < E/4
        int4 d4 = ((const int4*)dst)[idx];
        atomicAdd(&g_degE[d4.x], 1);
        atomicAdd(&g_degE[d4.y], 1);
        atomicAdd(&g_degE[d4.z], 1);
        atomicAdd(&g_degE[d4.w], 1);
    }
}

// K2: dinv = rsqrt(1+degE); hd = h*dinv; score = hd*dinv + b; reset degE
__global__ void k_dinv(const float* __restrict__ b) {
    int i = blockIdx.x * blockDim.x + threadIdx.x;
    float dv = rsqrtf(1.0f + (float)g_degE[i]);
    g_dinv[i] = dv;
    float hd = g_h[i] * dv;
    g_h[i] = hd;
    g_score[i] = hd * dv + b[0];
    g_degE[i] = 0;
}

// K3: score[d] += hd[s] * dinv[d]  (8 edges/thread, MLP~8; per-edge product
// matches reference rounding — do NOT factor dinv out of the sum)
__global__ void k_scatter(const int* __restrict__ src, const int* __restrict__ dst) {
    int idx = blockIdx.x * blockDim.x + threadIdx.x;    // < E/8
    const int4* s4p = (const int4*)src;
    const int4* d4p = (const int4*)dst;
    int4 sa = s4p[2 * idx], sb = s4p[2 * idx + 1];
    int4 da = d4p[2 * idx], db = d4p[2 * idx + 1];
    float h0 = g_h[sa.x], h1 = g_h[sa.y], h2 = g_h[sa.z], h3 = g_h[sa.w];
    float h4 = g_h[sb.x], h5 = g_h[sb.y], h6 = g_h[sb.z], h7 = g_h[sb.w];
    float v0 = g_dinv[da.x], v1 = g_dinv[da.y], v2 = g_dinv[da.z], v3 = g_dinv[da.w];
    float v4 = g_dinv[db.x], v5 = g_dinv[db.y], v6 = g_dinv[db.z], v7 = g_dinv[db.w];
    atomicAdd(&g_score[da.x], h0 * v0);
    atomicAdd(&g_score[da.y], h1 * v1);
    atomicAdd(&g_score[da.z], h2 * v2);
    atomicAdd(&g_score[da.w], h3 * v3);
    atomicAdd(&g_score[db.x], h4 * v4);
    atomicAdd(&g_score[db.y], h5 * v5);
    atomicAdd(&g_score[db.z], h6 * v6);
    atomicAdd(&g_score[db.w], h7 * v7);
}

// K4: per-graph top-k bitonic sort, ALL stages via warp shuffles.
// Cross-warp stages (j>=32) run in a transposed layout where element index
// bits [9:5] map to lane bits, so partner exchange is shfl_xor(j>>5).
// Key: (~monotone(score) << 32) | idx  -> ascending key == (desc score, asc idx)
__global__ void k_topk(float* __restrict__ out) {
    __shared__ unsigned long long keys[NPGc + (NPGc >> 5)];
#define PADI(i) ((i) + ((i) >> 5))
    int g = blockIdx.x, t = threadIdx.x;
    int w = t >> 5, l = t & 31;
    int node = g * NPGc + t;
    float sc = g_score[node];
    unsigned int u = __float_as_uint(sc);
    u = (u & 0x80000000u) ? ~u : (u | 0x80000000u);
    u = ~u;
    unsigned long long v = ((unsigned long long)u << 32) | (unsigned int)t;

    // k = 2..32: fully in-warp (element index == t)
#pragma unroll
    for (int k = 2; k <= 32; k <<= 1) {
        bool up = ((t & k) == 0);
#pragma unroll
        for (int j = k >> 1; j >= 1; j >>= 1) {
            unsigned long long o = __shfl_xor_sync(0xffffffffu, v, j);
            bool keepmin = (up == ((t & j) == 0));
            if (keepmin ? (o < v) : (o > v)) v = o;
        }
    }
    keys[PADI(t)] = v;
    __syncthreads();

    int eT = l * 32 + w;                    // element held in transposed phase
    for (int k = 64; k <= NPGc; k <<= 1) {
        // transposed phase: stages j = k/2 .. 32 as in-warp shuffles
        unsigned long long vt = keys[PADI(eT)];
        bool upT = ((eT & k) == 0);
        for (int j = k >> 1; j >= 32; j >>= 1) {
            unsigned long long o = __shfl_xor_sync(0xffffffffu, vt, j >> 5);
            bool keepmin = (upT == ((eT & j) == 0));
            if (keepmin ? (o < vt) : (o > vt)) vt = o;
        }
        keys[PADI(eT)] = vt;
        __syncthreads();
        // normal phase: stages j = 16..1
        v = keys[PADI(t)];
        bool up = ((t & k) == 0);
#pragma unroll
        for (int j = 16; j >= 1; j >>= 1) {
            unsigned long long o = __shfl_xor_sync(0xffffffffu, v, j);
            bool keepmin = (up == ((t & j) == 0));
            if (keepmin ? (o < v) : (o > v)) v = o;
        }
        if (k < NPGc) {
            keys[PADI(t)] = v;
            __syncthreads();
        }
    }

    if (t < KKc) {
        int li = (int)(v & 0xFFFFFFFFu);
        int n2 = g * NPGc + li;
        int p = g * KKc + t;
        g_perm[p] = n2;
        g_newidx[n2] = p;
        out[OFF_PERM + p]  = (float)n2;
        out[OFF_BATCH + p] = (float)g;
    }
#undef PADI
}

#define GATHER_BLOCKS 16384
#define EDGE_BLOCKS   8192

// K5: fused epilogue: x_new gather || ei remap + mask + masked ea copy
__global__ void k_epilogue(const float* __restrict__ x,
                           const int* __restrict__ src, const int* __restrict__ dst,
                           const float* __restrict__ ea, float* __restrict__ out) {
    if (blockIdx.x < GATHER_BLOCKS) {
        int row  = blockIdx.x * 2 + (threadIdx.x >> 7);
        int col4 = threadIdx.x & 127;
        int srcn = g_perm[row];
        float sc = tanhf(g_score[srcn]);
        float4 v = ((const float4*)(x + (size_t)srcn * CCc))[col4];
        v.x *= sc; v.y *= sc; v.z *= sc; v.w *= sc;
        ((float4*)(out + OFF_XNEW + (size_t)row * CCc))[col4] = v;
    } else {
        int wg   = ((blockIdx.x - GATHER_BLOCKS) * 256 + threadIdx.x) >> 5;
        int lane = threadIdx.x & 31;
        int e = wg * 32 + lane;
        int ns = g_newidx[src[e]];
        int nd = g_newidx[dst[e]];
        bool m = (ns >= 0) && (nd >= 0);
        out[OFF_EI + e]       = m ? (float)ns : -1.0f;
        out[OFF_EI + EEc + e] = m ? (float)nd : -1.0f;
        out[OFF_MASK + e]     = m ? 1.0f : 0.0f;
        unsigned mb = __ballot_sync(0xffffffffu, m);
        long base = (long)wg * 128;
        const float4* eav = (const float4*)ea;
        float4* outv = (float4*)(out + OFF_EA);
#pragma unroll
        for (int it = 0; it < 4; it++) {
            int tt = it * 32 + lane;
            bool mm = (mb >> (tt >> 2)) & 1u;
            float4 vv = make_float4(0.f, 0.f, 0.f, 0.f);
            if (mm) vv = eav[base + tt];
            outv[base + tt] = vv;
        }
    }
}

extern "C" void kernel_launch(void* const* d_in, const int* in_sizes, int n_in,
                              void* d_out, int out_size) {
    const float* x   = (const float*)d_in[0];
    const int*   ei  = (const int*)d_in[1];
    const float* ea  = (const float*)d_in[2];
    const float* W   = (const float*)d_in[4];
    const float* b   = (const float*)d_in[5];
    float* out = (float*)d_out;

    const int* src = ei;
    const int* dst = ei + EEc;

    k_proj_deg<<<PROJ_BLOCKS + DEG_BLOCKS, 256>>>(x, W, dst);
    k_dinv    <<<NN / 256, 256>>>(b);
    k_scatter <<<(EEc / 8) / 256, 256>>>(src, dst);
    k_topk    <<<BB, NPGc>>>(out);
    k_epilogue<<<GATHER_BLOCKS + EDGE_BLOCKS, 256>>>(x, src, dst, ea, out);
}

// round 7
// speedup vs baseline: 1.0149x; 1.0149x over previous
#include <cuda_runtime.h>

// Problem constants (fixed shapes)
#define NN   65536
#define BB   64
#define NPGc 1024
#define CCc  512
#define EEc  2097152
#define DEc  16
#define KKc  512
#define BKc  32768

// Output layout (float32, reference-return order)
#define OFF_XNEW  0LL
#define OFF_EI    16777216LL
#define OFF_EA    20971520LL
#define OFF_MASK  54525952LL
#define OFF_BATCH 56623104LL
#define OFF_PERM  56655872LL

// Scratch. Invariant: g_degE is zero at entry and restored each replay.
// g_scoreD is rewritten fresh by k_dinv each replay before scatter adds.
__device__ float  g_h[NN];        // h = x@W (raw, NOT pre-scaled)
__device__ float  g_dinv[NN];
__device__ double g_scoreD[NN];   // order-independent (double) score accumulator
__device__ float  g_score[NN];    // final float score (written by k_topk)
__device__ int    g_degE[NN];
__device__ int    g_newidx[NN];
__device__ int    g_perm[BKc];

#define PROJ_BLOCKS 8192
#define DEG_BLOCKS  2048

// K1: fused  h = x@W (warp/row)  ||  in-degree atomics (4 edges/thread)
__global__ void k_proj_deg(const float* __restrict__ x, const float* __restrict__ W,
                           const int* __restrict__ dst) {
    if (blockIdx.x < PROJ_BLOCKS) {
        int warp = (blockIdx.x * blockDim.x + threadIdx.x) >> 5;
        int lane = threadIdx.x & 31;
        const float4* xr = (const float4*)(x + (size_t)warp * CCc);
        const float4* w4 = (const float4*)W;
        float s = 0.f;
#pragma unroll
        for (int i = 0; i < 4; i++) {
            float4 a = xr[lane + i * 32];
            float4 w = w4[lane + i * 32];
            s += a.x * w.x + a.y * w.y + a.z * w.z + a.w * w.w;
        }
#pragma unroll
        for (int o = 16; o; o >>= 1) s += __shfl_down_sync(0xffffffffu, s, o);
        if (lane == 0) {
            g_h[warp] = s;
            g_newidx[warp] = -1;
        }
    } else {
        int idx = (blockIdx.x - PROJ_BLOCKS) * 256 + threadIdx.x;   // < E/4
        int4 d4 = ((const int4*)dst)[idx];
        atomicAdd(&g_degE[d4.x], 1);
        atomicAdd(&g_degE[d4.y], 1);
        atomicAdd(&g_degE[d4.z], 1);
        atomicAdd(&g_degE[d4.w], 1);
    }
}

// K2: dinv = rsqrt(1+degE); scoreD = h * (dinv*dinv)  [reference term rounding];
//     reset degE
__global__ void k_dinv() {
    int i = blockIdx.x * blockDim.x + threadIdx.x;
    float dv = rsqrtf(1.0f + (float)g_degE[i]);
    g_dinv[i] = dv;
    float t = __fmul_rn(g_h[i], __fmul_rn(dv, dv));
    g_scoreD[i] = (double)t;
    g_degE[i] = 0;
}

// K3: scoreD[d] += (double)( h[s] * (dinv[s]*dinv[d]) )
// Per-term float rounding matches the reference EXACTLY; double accumulation
// makes the sum order-independent -> deterministic ranking across replays.
__global__ void k_scatter(const int* __restrict__ src, const int* __restrict__ dst) {
    int idx = blockIdx.x * blockDim.x + threadIdx.x;    // < E/4
    int4 s4 = ((const int4*)src)[idx];
    int4 d4 = ((const int4*)dst)[idx];
    float h0 = g_h[s4.x], h1 = g_h[s4.y], h2 = g_h[s4.z], h3 = g_h[s4.w];
    float a0 = g_dinv[s4.x], a1 = g_dinv[s4.y], a2 = g_dinv[s4.z], a3 = g_dinv[s4.w];
    float b0 = g_dinv[d4.x], b1 = g_dinv[d4.y], b2 = g_dinv[d4.z], b3 = g_dinv[d4.w];
    float t0 = __fmul_rn(h0, __fmul_rn(a0, b0));
    float t1 = __fmul_rn(h1, __fmul_rn(a1, b1));
    float t2 = __fmul_rn(h2, __fmul_rn(a2, b2));
    float t3 = __fmul_rn(h3, __fmul_rn(a3, b3));
    atomicAdd(&g_scoreD[d4.x], (double)t0);
    atomicAdd(&g_scoreD[d4.y], (double)t1);
    atomicAdd(&g_scoreD[d4.z], (double)t2);
    atomicAdd(&g_scoreD[d4.w], (double)t3);
}

// K4: per-graph top-k via hybrid bitonic sort (R4 version):
//   j<=16 stages in registers via shfl_xor, j>=32 in shared.
__global__ void k_topk(const float* __restrict__ b, float* __restrict__ out) {
    __shared__ unsigned long long keys[NPGc];
    int g = blockIdx.x, t = threadIdx.x;
    int node = g * NPGc + t;
    float sc = (float)g_scoreD[node] + b[0];
    g_score[node] = sc;
    unsigned int u = __float_as_uint(sc);
    u = (u & 0x80000000u) ? ~u : (u | 0x80000000u);
    u = ~u;
    unsigned long long v = ((unsigned long long)u << 32) | (unsigned int)t;

#pragma unroll
    for (int k = 2; k <= 32; k <<= 1) {
        bool up = ((t & k) == 0);
#pragma unroll
        for (int j = k >> 1; j >= 1; j >>= 1) {
            unsigned long long o = __shfl_xor_sync(0xffffffffu, v, j);
            bool keepmin = (up == ((t & j) == 0));
            if (keepmin ? (o < v) : (o > v)) v = o;
        }
    }
    keys[t] = v;
    __syncthreads();

    for (int k = 64; k <= NPGc; k <<= 1) {
        bool up = ((t & k) == 0);
        for (int j = k >> 1; j >= 32; j >>= 1) {
            int ixj = t ^ j;
            if (ixj > t) {
                unsigned long long a = keys[t], bb = keys[ixj];
                if ((a > bb) == up) { keys[t] = bb; keys[ixj] = a; }
            }
            __syncthreads();
        }
        v = keys[t];
#pragma unroll
        for (int j = 16; j >= 1; j >>= 1) {
            unsigned long long o = __shfl_xor_sync(0xffffffffu, v, j);
            bool keepmin = (up == ((t & j) == 0));
            if (keepmin ? (o < v) : (o > v)) v = o;
        }
        keys[t] = v;
        __syncthreads();
    }

    if (t < KKc) {
        int li = (int)(keys[t] & 0xFFFFFFFFu);
        int n2 = g * NPGc + li;
        int p = g * KKc + t;
        g_perm[p] = n2;
        g_newidx[n2] = p;
        out[OFF_PERM + p]  = (float)n2;
        out[OFF_BATCH + p] = (float)g;
    }
}

#define GATHER_BLOCKS 16384
#define EDGE_BLOCKS   2048      // 1024 edges/block, 4 edges/thread (int4)

// K5: fused epilogue: x_new gather || ei remap (int4/float4) + mask + masked ea copy
__global__ void k_epilogue(const float* __restrict__ x,
                           const int* __restrict__ src, const int* __restrict__ dst,
                           const float* __restrict__ ea, float* __restrict__ out) {
    if (blockIdx.x < GATHER_BLOCKS) {
        int row  = blockIdx.x * 2 + (threadIdx.x >> 7);
        int col4 = threadIdx.x & 127;
        int srcn = g_perm[row];
        float sc = tanhf(g_score[srcn]);
        float4 v = ((const float4*)(x + (size_t)srcn * CCc))[col4];
        v.x *= sc; v.y *= sc; v.z *= sc; v.w *= sc;
        ((float4*)(out + OFF_XNEW + (size_t)row * CCc))[col4] = v;
    } else {
        int e4   = (blockIdx.x - GATHER_BLOCKS) * 256 + threadIdx.x;   // < E/4
        int lane = threadIdx.x & 31;
        int4 s4 = ((const int4*)src)[e4];
        int4 d4 = ((const int4*)dst)[e4];
        int ns0 = g_newidx[s4.x], ns1 = g_newidx[s4.y], ns2 = g_newidx[s4.z], ns3 = g_newidx[s4.w];
        int nd0 = g_newidx[d4.x], nd1 = g_newidx[d4.y], nd2 = g_newidx[d4.z], nd3 = g_newidx[d4.w];
        bool m0 = (ns0 >= 0) && (nd0 >= 0);
        bool m1 = (ns1 >= 0) && (nd1 >= 0);
        bool m2 = (ns2 >= 0) && (nd2 >= 0);
        bool m3 = (ns3 >= 0) && (nd3 >= 0);
        float4 eis = make_float4(m0 ? (float)ns0 : -1.f, m1 ? (float)ns1 : -1.f,
                                 m2 ? (float)ns2 : -1.f, m3 ? (float)ns3 : -1.f);
        float4 eid = make_float4(m0 ? (float)nd0 : -1.f, m1 ? (float)nd1 : -1.f,
                                 m2 ? (float)nd2 : -1.f, m3 ? (float)nd3 : -1.f);
        float4 msk = make_float4(m0 ? 1.f : 0.f, m1 ? 1.f : 0.f,
                                 m2 ? 1.f : 0.f, m3 ? 1.f : 0.f);
        ((float4*)(out + OFF_EI))[e4]       = eis;
        ((float4*)(out + OFF_EI + EEc))[e4] = eid;
        ((float4*)(out + OFF_MASK))[e4]     = msk;
        // ea: warp covers 128 edges = 512 float4s; per-thread 4 mask bits
        unsigned mm = ((unsigned)m0) | ((unsigned)m1 << 1) | ((unsigned)m2 << 2) | ((unsigned)m3 << 3);
        long warpQuadBase = (long)(e4 - lane) * 16;
        const float4* eav = (const float4*)ea;
        float4* outv = (float4*)(out + OFF_EA);
#pragma unroll
        for (int half = 0; half < 4; half++) {
            int eIdx = half * 32 + lane;
            unsigned srcbits = __shfl_sync(0xffffffffu, mm, eIdx >> 2);
            bool me = (srcbits >> (eIdx & 3)) & 1u;
            unsigned bmask = __ballot_sync(0xffffffffu, me);
#pragma unroll
            for (int it = 0; it < 4; it++) {
                int tt = it * 32 + lane;
                bool keep = (bmask >> (tt >> 2)) & 1u;
                long o = warpQuadBase + (long)half * 128 + tt;
                float4 vv = make_float4(0.f, 0.f, 0.f, 0.f);
                if (keep) vv = eav[o];
                outv[o] = vv;
            }
        }
    }
}

extern "C" void kernel_launch(void* const* d_in, const int* in_sizes, int n_in,
                              void* d_out, int out_size) {
    const float* x   = (const float*)d_in[0];
    const int*   ei  = (const int*)d_in[1];
    const float* ea  = (const float*)d_in[2];
    const float* W   = (const float*)d_in[4];
    const float* b   = (const float*)d_in[5];
    float* out = (float*)d_out;

    const int* src = ei;
    const int* dst = ei + EEc;

    k_proj_deg<<<PROJ_BLOCKS + DEG_BLOCKS, 256>>>(x, W, dst);
    k_dinv    <<<NN / 256, 256>>>();
    k_scatter <<<(EEc / 4) / 256, 256>>>(src, dst);
    k_topk    <<<BB, NPGc>>>(b, out);
    k_epilogue<<<GATHER_BLOCKS + EDGE_BLOCKS, 256>>>(x, src, dst, ea, out);
}

// round 8
// speedup vs baseline: 1.0287x; 1.0136x over previous
#include <cuda_runtime.h>

// Problem constants (fixed shapes)
#define NN   65536
#define BB   64
#define NPGc 1024
#define CCc  512
#define EEc  2097152
#define DEc  16
#define KKc  512
#define BKc  32768

// Output layout (float32, reference-return order)
#define OFF_XNEW  0LL
#define OFF_EI    16777216LL
#define OFF_EA    20971520LL
#define OFF_MASK  54525952LL
#define OFF_BATCH 56623104LL
#define OFF_PERM  56655872LL

// Scratch. Invariant: g_degE is zero at entry and restored each replay.
// g_scoreD is rewritten fresh by k_dinv each replay before scatter adds.
__device__ float  g_h[NN];        // h = x@W (raw)
__device__ float2 g_hd[NN];       // (h, dinv) packed — one gather per src node
__device__ double g_scoreD[NN];   // order-independent (double) score accumulator
__device__ float  g_score[NN];    // final float score (written by k_topk)
__device__ int    g_degE[NN];
__device__ int    g_newidx[NN];
__device__ int    g_perm[BKc];

#define PROJ_BLOCKS 8192
#define DEG_BLOCKS  1024        // (E/8)/256

// K1: fused  h = x@W (warp/row)  ||  in-degree atomics (8 edges/thread;
// int atomics are order-independent, widening is numerics-safe)
__global__ void k_proj_deg(const float* __restrict__ x, const float* __restrict__ W,
                           const int* __restrict__ dst) {
    if (blockIdx.x < PROJ_BLOCKS) {
        int warp = (blockIdx.x * blockDim.x + threadIdx.x) >> 5;
        int lane = threadIdx.x & 31;
        const float4* xr = (const float4*)(x + (size_t)warp * CCc);
        const float4* w4 = (const float4*)W;
        float s = 0.f;
#pragma unroll
        for (int i = 0; i < 4; i++) {
            float4 a = xr[lane + i * 32];
            float4 w = w4[lane + i * 32];
            s += a.x * w.x + a.y * w.y + a.z * w.z + a.w * w.w;
        }
#pragma unroll
        for (int o = 16; o; o >>= 1) s += __shfl_down_sync(0xffffffffu, s, o);
        if (lane == 0) {
            g_h[warp] = s;
            g_newidx[warp] = -1;
        }
    } else {
        int idx = (blockIdx.x - PROJ_BLOCKS) * 256 + threadIdx.x;   // < E/8
        int4 da = ((const int4*)dst)[2 * idx];
        int4 db = ((const int4*)dst)[2 * idx + 1];
        atomicAdd(&g_degE[da.x], 1);
        atomicAdd(&g_degE[da.y], 1);
        atomicAdd(&g_degE[da.z], 1);
        atomicAdd(&g_degE[da.w], 1);
        atomicAdd(&g_degE[db.x], 1);
        atomicAdd(&g_degE[db.y], 1);
        atomicAdd(&g_degE[db.z], 1);
        atomicAdd(&g_degE[db.w], 1);
    }
}

// K2: dinv = rsqrt(1+degE); pack (h,dinv); scoreD = h*(dinv*dinv); reset degE
__global__ void k_dinv() {
    int i = blockIdx.x * blockDim.x + threadIdx.x;
    float dv = rsqrtf(1.0f + (float)g_degE[i]);
    float h = g_h[i];
    g_hd[i] = make_float2(h, dv);
    g_scoreD[i] = (double)__fmul_rn(h, __fmul_rn(dv, dv));
    g_degE[i] = 0;
}

// K3: scoreD[d] += (double)( h[s] * (dinv[s]*dinv[d]) )   — 8 edges/thread.
// Per-term float rounding matches the reference EXACTLY; double accumulation
// makes the sum order-independent, so issue order/width is free to change.
__global__ void k_scatter(const int* __restrict__ src, const int* __restrict__ dst) {
    int idx = blockIdx.x * blockDim.x + threadIdx.x;    // < E/8
    int4 sa = ((const int4*)src)[2 * idx];
    int4 sb = ((const int4*)src)[2 * idx + 1];
    int4 da = ((const int4*)dst)[2 * idx];
    int4 db = ((const int4*)dst)[2 * idx + 1];
    float2 p0 = g_hd[sa.x], p1 = g_hd[sa.y], p2 = g_hd[sa.z], p3 = g_hd[sa.w];
    float2 p4 = g_hd[sb.x], p5 = g_hd[sb.y], p6 = g_hd[sb.z], p7 = g_hd[sb.w];
    float d0 = g_hd[da.x].y, d1 = g_hd[da.y].y, d2 = g_hd[da.z].y, d3 = g_hd[da.w].y;
    float d4 = g_hd[db.x].y, d5 = g_hd[db.y].y, d6 = g_hd[db.z].y, d7 = g_hd[db.w].y;
    atomicAdd(&g_scoreD[da.x], (double)__fmul_rn(p0.x, __fmul_rn(p0.y, d0)));
    atomicAdd(&g_scoreD[da.y], (double)__fmul_rn(p1.x, __fmul_rn(p1.y, d1)));
    atomicAdd(&g_scoreD[da.z], (double)__fmul_rn(p2.x, __fmul_rn(p2.y, d2)));
    atomicAdd(&g_scoreD[da.w], (double)__fmul_rn(p3.x, __fmul_rn(p3.y, d3)));
    atomicAdd(&g_scoreD[db.x], (double)__fmul_rn(p4.x, __fmul_rn(p4.y, d4)));
    atomicAdd(&g_scoreD[db.y], (double)__fmul_rn(p5.x, __fmul_rn(p5.y, d5)));
    atomicAdd(&g_scoreD[db.z], (double)__fmul_rn(p6.x, __fmul_rn(p6.y, d6)));
    atomicAdd(&g_scoreD[db.w], (double)__fmul_rn(p7.x, __fmul_rn(p7.y, d7)));
}

// K4: per-graph top-k via hybrid bitonic sort (R4/R7 version, proven):
//   j<=16 stages in registers via shfl_xor, j>=32 in shared.
__global__ void k_topk(const float* __restrict__ b, float* __restrict__ out) {
    __shared__ unsigned long long keys[NPGc];
    int g = blockIdx.x, t = threadIdx.x;
    int node = g * NPGc + t;
    float sc = (float)g_scoreD[node] + b[0];
    g_score[node] = sc;
    unsigned int u = __float_as_uint(sc);
    u = (u & 0x80000000u) ? ~u : (u | 0x80000000u);
    u = ~u;
    unsigned long long v = ((unsigned long long)u << 32) | (unsigned int)t;

#pragma unroll
    for (int k = 2; k <= 32; k <<= 1) {
        bool up = ((t & k) == 0);
#pragma unroll
        for (int j = k >> 1; j >= 1; j >>= 1) {
            unsigned long long o = __shfl_xor_sync(0xffffffffu, v, j);
            bool keepmin = (up == ((t & j) == 0));
            if (keepmin ? (o < v) : (o > v)) v = o;
        }
    }
    keys[t] = v;
    __syncthreads();

    for (int k = 64; k <= NPGc; k <<= 1) {
        bool up = ((t & k) == 0);
        for (int j = k >> 1; j >= 32; j >>= 1) {
            int ixj = t ^ j;
            if (ixj > t) {
                unsigned long long a = keys[t], bb = keys[ixj];
                if ((a > bb) == up) { keys[t] = bb; keys[ixj] = a; }
            }
            __syncthreads();
        }
        v = keys[t];
#pragma unroll
        for (int j = 16; j >= 1; j >>= 1) {
            unsigned long long o = __shfl_xor_sync(0xffffffffu, v, j);
            bool keepmin = (up == ((t & j) == 0));
            if (keepmin ? (o < v) : (o > v)) v = o;
        }
        keys[t] = v;
        __syncthreads();
    }

    if (t < KKc) {
        int li = (int)(keys[t] & 0xFFFFFFFFu);
        int n2 = g * NPGc + li;
        int p = g * KKc + t;
        g_perm[p] = n2;
        g_newidx[n2] = p;
        out[OFF_PERM + p]  = (float)n2;
        out[OFF_BATCH + p] = (float)g;
    }
}

#define GATHER_BLOCKS 16384
#define EDGE_BLOCKS   2048      // 1024 edges/block, 4 edges/thread (int4)

// K5: fused epilogue: x_new gather || ei remap (int4/float4) + mask + masked ea copy
__global__ void k_epilogue(const float* __restrict__ x,
                           const int* __restrict__ src, const int* __restrict__ dst,
                           const float* __restrict__ ea, float* __restrict__ out) {
    if (blockIdx.x < GATHER_BLOCKS) {
        int row  = blockIdx.x * 2 + (threadIdx.x >> 7);
        int col4 = threadIdx.x & 127;
        int srcn = g_perm[row];
        float sc = tanhf(g_score[srcn]);
        float4 v = ((const float4*)(x + (size_t)srcn * CCc))[col4];
        v.x *= sc; v.y *= sc; v.z *= sc; v.w *= sc;
        ((float4*)(out + OFF_XNEW + (size_t)row * CCc))[col4] = v;
    } else {
        int e4   = (blockIdx.x - GATHER_BLOCKS) * 256 + threadIdx.x;   // < E/4
        int lane = threadIdx.x & 31;
        int4 s4 = ((const int4*)src)[e4];
        int4 d4 = ((const int4*)dst)[e4];
        int ns0 = g_newidx[s4.x], ns1 = g_newidx[s4.y], ns2 = g_newidx[s4.z], ns3 = g_newidx[s4.w];
        int nd0 = g_newidx[d4.x], nd1 = g_newidx[d4.y], nd2 = g_newidx[d4.z], nd3 = g_newidx[d4.w];
        bool m0 = (ns0 >= 0) && (nd0 >= 0);
        bool m1 = (ns1 >= 0) && (nd1 >= 0);
        bool m2 = (ns2 >= 0) && (nd2 >= 0);
        bool m3 = (ns3 >= 0) && (nd3 >= 0);
        float4 eis = make_float4(m0 ? (float)ns0 : -1.f, m1 ? (float)ns1 : -1.f,
                                 m2 ? (float)ns2 : -1.f, m3 ? (float)ns3 : -1.f);
        float4 eid = make_float4(m0 ? (float)nd0 : -1.f, m1 ? (float)nd1 : -1.f,
                                 m2 ? (float)nd2 : -1.f, m3 ? (float)nd3 : -1.f);
        float4 msk = make_float4(m0 ? 1.f : 0.f, m1 ? 1.f : 0.f,
                                 m2 ? 1.f : 0.f, m3 ? 1.f : 0.f);
        ((float4*)(out + OFF_EI))[e4]       = eis;
        ((float4*)(out + OFF_EI + EEc))[e4] = eid;
        ((float4*)(out + OFF_MASK))[e4]     = msk;
        unsigned mm = ((unsigned)m0) | ((unsigned)m1 << 1) | ((unsigned)m2 << 2) | ((unsigned)m3 << 3);
        long warpQuadBase = (long)(e4 - lane) * 16;
        const float4* eav = (const float4*)ea;
        float4* outv = (float4*)(out + OFF_EA);
#pragma unroll
        for (int half = 0; half < 4; half++) {
            int eIdx = half * 32 + lane;
            unsigned srcbits = __shfl_sync(0xffffffffu, mm, eIdx >> 2);
            bool me = (srcbits >> (eIdx & 3)) & 1u;
            unsigned bmask = __ballot_sync(0xffffffffu, me);
#pragma unroll
            for (int it = 0; it < 4; it++) {
                int tt = it * 32 + lane;
                bool keep = (bmask >> (tt >> 2)) & 1u;
                long o = warpQuadBase + (long)half * 128 + tt;
                float4 vv = make_float4(0.f, 0.f, 0.f, 0.f);
                if (keep) vv = eav[o];
                outv[o] = vv;
            }
        }
    }
}

extern "C" void kernel_launch(void* const* d_in, const int* in_sizes, int n_in,
                              void* d_out, int out_size) {
    const float* x   = (const float*)d_in[0];
    const int*   ei  = (const int*)d_in[1];
    const float* ea  = (const float*)d_in[2];
    const float* W   = (const float*)d_in[4];
    const float* b   = (const float*)d_in[5];
    float* out = (float*)d_out;

    const int* src = ei;
    const int* dst = ei + EEc;

    k_proj_deg<<<PROJ_BLOCKS + DEG_BLOCKS, 256>>>(x, W, dst);
    k_dinv    <<<NN / 256, 256>>>();
    k_scatter <<<(EEc / 8) / 256, 256>>>(src, dst);
    k_topk    <<<BB, NPGc>>>(b, out);
    k_epilogue<<<GATHER_BLOCKS + EDGE_BLOCKS, 256>>>(x, src, dst, ea, out);
}